// round 1
// baseline (speedup 1.0000x reference)
#include <cuda_runtime.h>
#include <math.h>

#define NTOT   32768
#define EDG    524288
#define HD     256
#define HEADS  8
#define CDIM   32
#define GRAPHS 64
#define NPG    512
#define CAP    128   // max in-degree capacity (Poisson(16): max deg ~45, huge margin)

// ----------------------------- scratch (static device) -----------------------------
__device__ __align__(16) float g_xl[NTOT*HD];
__device__ __align__(16) float g_xr[NTOT*HD];
__device__ __align__(16) float g_qkv[NTOT*3*HD];
__device__ __align__(16) float g_attno[NTOT*HD];
__device__ __align__(16) float g_graw[NTOT*HD];
__device__ __align__(16) float g_local[NTOT*HD];
__device__ __align__(16) float g_comb[NTOT*HD];
__device__ __align__(16) float g_h1[NTOT*4*HD];
__device__ __align__(16) float g_f2[NTOT*HD];
__device__ int   g_deg[NTOT];
__device__ int   g_off[NTOT];
__device__ int   g_cur[NTOT];
__device__ int   g_csr[EDG];
__device__ float g_easum[NTOT*2];

// ----------------------------- helpers -----------------------------
__device__ __forceinline__ unsigned long long pk2(float a, float b){
    unsigned long long r;
    asm("mov.b64 %0,{%1,%2};" : "=l"(r) : "r"(__float_as_uint(a)), "r"(__float_as_uint(b)));
    return r;
}
__device__ __forceinline__ void upk2(unsigned long long v, float &a, float &b){
    unsigned int x, y;
    asm("mov.b64 {%0,%1},%2;" : "=r"(x), "=r"(y) : "l"(v));
    a = __uint_as_float(x); b = __uint_as_float(y);
}
__device__ __forceinline__ void fma2(unsigned long long &d, unsigned long long a, unsigned long long b){
    asm("fma.rn.f32x2 %0,%1,%2,%0;" : "+l"(d) : "l"(a), "l"(b));
}
__device__ __forceinline__ float geluf(float x){
    return 0.5f * x * (1.0f + erff(x * 0.70710678118654752f));
}
// block-wide sum for blockDim.x == 256 (8 warps). red: shared float[8].
__device__ __forceinline__ float blocksum256(float v, float* red){
    int lane = threadIdx.x & 31, wid = threadIdx.x >> 5;
    #pragma unroll
    for (int o = 16; o; o >>= 1) v += __shfl_xor_sync(0xffffffffu, v, o);
    if (lane == 0) red[wid] = v;
    __syncthreads();
    float r = (threadIdx.x < 8) ? red[threadIdx.x] : 0.0f;
    if (wid == 0) {
        #pragma unroll
        for (int o = 4; o; o >>= 1) r += __shfl_xor_sync(0xffffffffu, r, o);
        if (lane == 0) red[0] = r;
    }
    __syncthreads();
    float out = red[0];
    __syncthreads();   // protect red[] reuse by next call
    return out;
}

// ----------------------------- tiny graph kernels -----------------------------
__global__ void k_zero(){
    int i = blockIdx.x * blockDim.x + threadIdx.x;
    if (i < NTOT) { g_deg[i] = 0; g_cur[i] = 0; g_easum[2*i] = 0.f; g_easum[2*i+1] = 0.f; }
}
__global__ void k_edgecnt(const int* __restrict__ ei, const float* __restrict__ ea){
    int e = blockIdx.x * blockDim.x + threadIdx.x;
    if (e < EDG) {
        int d = ei[EDG + e];
        atomicAdd(&g_deg[d], 1);
        atomicAdd(&g_easum[2*d],     ea[2*e]);
        atomicAdd(&g_easum[2*d + 1], ea[2*e + 1]);
    }
}
// exclusive prefix sum over deg[32768], one block of 1024 threads, 32 elems/thread
__global__ void k_scan(){
    __shared__ int wsum[32];
    int tid = threadIdx.x;
    int base = tid * 32;
    int loc[32]; int s = 0;
    #pragma unroll
    for (int t = 0; t < 32; t++) { loc[t] = s; s += g_deg[base + t]; }
    int lane = tid & 31, wid = tid >> 5;
    int v = s;
    #pragma unroll
    for (int o = 1; o < 32; o <<= 1) { int n = __shfl_up_sync(0xffffffffu, v, o); if (lane >= o) v += n; }
    if (lane == 31) wsum[wid] = v;
    __syncthreads();
    if (wid == 0) {
        int w = wsum[lane];
        #pragma unroll
        for (int o = 1; o < 32; o <<= 1) { int n = __shfl_up_sync(0xffffffffu, w, o); if (lane >= o) w += n; }
        wsum[lane] = w;
    }
    __syncthreads();
    int chunk_base = v - s + (wid ? wsum[wid - 1] : 0);
    #pragma unroll
    for (int t = 0; t < 32; t++) g_off[base + t] = chunk_base + loc[t];
}
__global__ void k_fill(const int* __restrict__ ei){
    int e = blockIdx.x * blockDim.x + threadIdx.x;
    if (e < EDG) {
        int d = ei[EDG + e];
        int p = atomicAdd(&g_cur[d], 1);
        g_csr[g_off[d] + p] = e;
    }
}

// ----------------------------- GATv2 per-node kernel (scores+softmax+agg+bias+LN1) -----------------------------
__global__ void __launch_bounds__(256) k_gat(const int* __restrict__ ei, const float* __restrict__ ea,
                                             const float* __restrict__ We, const float* __restrict__ att,
                                             const float* __restrict__ bias_gat,
                                             const float* __restrict__ g1, const float* __restrict__ be1)
{
    int i = blockIdx.x;
    int j = threadIdx.x;
    int h = j >> 5, lane = j & 31;
    __shared__ int   s_src[CAP];
    __shared__ float s_e0[CAP], s_e1[CAP];
    __shared__ float s_sc[(CAP + 1) * HEADS];
    __shared__ float s_Z[HEADS];
    __shared__ float s_red[8];

    int degr = g_deg[i];
    int deg  = degr > CAP ? CAP : degr;
    int off  = g_off[i];
    for (int k = j; k < deg; k += 256) {
        int eid = g_csr[off + k];
        s_src[k] = ei[eid];
        s_e0[k] = ea[2*eid];
        s_e1[k] = ea[2*eid + 1];
    }
    float xr_j = g_xr[i*HD + j];
    float xl_i = g_xl[i*HD + j];
    float we0 = We[j], we1 = We[HD + j];
    float attj = att[j];
    float dr = fmaxf((float)degr, 1.0f);
    float m0 = g_easum[2*i] / dr, m1 = g_easum[2*i + 1] / dr;
    __syncthreads();

    // pass 1: scores
    for (int k = 0; k <= deg; k++) {
        float xls, e0, e1;
        if (k < deg) { int s = s_src[k]; xls = g_xl[s*HD + j]; e0 = s_e0[k]; e1 = s_e1[k]; }
        else         { xls = xl_i; e0 = m0; e1 = m1; }
        float v = xls + xr_j + e0*we0 + e1*we1;
        v = v > 0.f ? v : 0.2f * v;
        float p = v * attj;
        #pragma unroll
        for (int o = 16; o; o >>= 1) p += __shfl_xor_sync(0xffffffffu, p, o);
        if (lane == 0) s_sc[k*HEADS + h] = p;
    }
    __syncthreads();

    // per-head softmax (8 threads, serial over <=CAP+1 entries)
    if (j < HEADS) {
        float m = -1e30f;
        for (int k = 0; k <= deg; k++) m = fmaxf(m, s_sc[k*HEADS + j]);
        float Z = 0.f;
        for (int k = 0; k <= deg; k++) { float e = __expf(s_sc[k*HEADS + j] - m); s_sc[k*HEADS + j] = e; Z += e; }
        s_Z[j] = Z;
    }
    __syncthreads();

    // pass 2: weighted aggregation
    float acc = 0.f;
    for (int k = 0; k < deg; k++) acc += s_sc[k*HEADS + h] * g_xl[s_src[k]*HD + j];
    acc += s_sc[deg*HEADS + h] * xl_i;
    float val = acc / s_Z[h] + bias_gat[j];

    // fused LN1
    float mean = blocksum256(val, s_red) * (1.0f / 256.0f);
    float d = val - mean;
    float var = blocksum256(d*d, s_red) * (1.0f / 256.0f);
    g_local[i*HD + j] = d * rsqrtf(var + 1e-5f) * g1[j] + be1[j];
}

// ----------------------------- generic GEMM with packed f32x2 FFMA -----------------------------
// C[M,N] = A[M,K] * B (+bias, +optional exact GELU).  TB=false: B is KxN row-major; TB=true: B is NxK (use B^T).
template<bool TB, bool ACT>
__global__ void __launch_bounds__(256) k_gemm(const float* __restrict__ A, const float* __restrict__ B,
                                              const float* __restrict__ bias, float* __restrict__ C,
                                              int M, int N, int K)
{
    __shared__ __align__(16) float As[16][128];
    __shared__ __align__(16) float Bs[16][128];
    int bm = blockIdx.y * 128, bn = blockIdx.x * 128;
    int tid = threadIdx.x, tx = tid & 15, ty = tid >> 4;

    unsigned long long acc[8][4];
    #pragma unroll
    for (int i = 0; i < 8; i++)
        #pragma unroll
        for (int q = 0; q < 4; q++) acc[i][q] = 0ull;

    for (int k0 = 0; k0 < K; k0 += 16) {
        #pragma unroll
        for (int t = 0; t < 2; t++) {
            int idx = tid + t*256;
            int row = idx >> 2, c4 = idx & 3;
            float4 av = *(const float4*)&A[(size_t)(bm + row)*K + k0 + c4*4];
            As[c4*4+0][row] = av.x; As[c4*4+1][row] = av.y;
            As[c4*4+2][row] = av.z; As[c4*4+3][row] = av.w;
        }
        if (!TB) {
            #pragma unroll
            for (int t = 0; t < 2; t++) {
                int idx = tid + t*256;
                int r = idx >> 5, c4 = idx & 31;
                float4 bv = *(const float4*)&B[(size_t)(k0 + r)*N + bn + c4*4];
                *(float4*)&Bs[r][c4*4] = bv;
            }
        } else {
            #pragma unroll
            for (int t = 0; t < 2; t++) {
                int idx = tid + t*256;
                int n = idx >> 2, kc = idx & 3;
                float4 bv = *(const float4*)&B[(size_t)(bn + n)*K + k0 + kc*4];
                Bs[kc*4+0][n] = bv.x; Bs[kc*4+1][n] = bv.y;
                Bs[kc*4+2][n] = bv.z; Bs[kc*4+3][n] = bv.w;
            }
        }
        __syncthreads();
        #pragma unroll
        for (int kk = 0; kk < 16; kk++) {
            float4 a0 = *(float4*)&As[kk][ty*4];
            float4 a1 = *(float4*)&As[kk][64 + ty*4];
            float4 b0 = *(float4*)&Bs[kk][tx*4];
            float4 b1 = *(float4*)&Bs[kk][64 + tx*4];
            unsigned long long bp[4] = { pk2(b0.x,b0.y), pk2(b0.z,b0.w), pk2(b1.x,b1.y), pk2(b1.z,b1.w) };
            float a[8] = { a0.x,a0.y,a0.z,a0.w, a1.x,a1.y,a1.z,a1.w };
            #pragma unroll
            for (int i = 0; i < 8; i++) {
                unsigned long long ad = pk2(a[i], a[i]);
                fma2(acc[i][0], ad, bp[0]);
                fma2(acc[i][1], ad, bp[1]);
                fma2(acc[i][2], ad, bp[2]);
                fma2(acc[i][3], ad, bp[3]);
            }
        }
        __syncthreads();
    }
    #pragma unroll
    for (int i = 0; i < 8; i++) {
        int gr = bm + ((i < 4) ? (ty*4 + i) : (64 + ty*4 + i - 4));
        #pragma unroll
        for (int q = 0; q < 2; q++) {
            int gc = bn + (q ? (64 + tx*4) : (tx*4));
            float v0, v1, v2, v3;
            upk2(acc[i][q*2 + 0], v0, v1);
            upk2(acc[i][q*2 + 1], v2, v3);
            v0 += bias[gc]; v1 += bias[gc+1]; v2 += bias[gc+2]; v3 += bias[gc+3];
            if (ACT) { v0 = geluf(v0); v1 = geluf(v1); v2 = geluf(v2); v3 = geluf(v3); }
            float4 o = { v0, v1, v2, v3 };
            *(float4*)&C[(size_t)gr*N + gc] = o;
        }
    }
}

// ----------------------------- fused MHA (one block per (graph, head)) -----------------------------
// smem: K [512][36] + V^T [32][516] + P [8 warps][4 rows][512]   = 205,312 B
#define ATTN_SMEM_BYTES ((18432 + 16512 + 16384) * 4)
__global__ void __launch_bounds__(256) k_attn()
{
    extern __shared__ float sm[];
    float* Ks = sm;                    // 512*36 floats
    float* Vt = sm + 18432;            // 32*516 floats
    float* Ps = sm + 18432 + 16512;    // 8*4*512 floats
    int gh = blockIdx.x;
    int g = gh >> 3, h = gh & 7;
    int tid = threadIdx.x, w = tid >> 5, lane = tid & 31;
    int gbase = g * NPG;

    for (int idx = tid; idx < NPG * CDIM; idx += 256) {
        int row = idx >> 5, c = idx & 31;
        size_t rb = (size_t)(gbase + row) * 768 + h*32 + c;
        Ks[row*36 + c]  = g_qkv[rb + 256];
        Vt[c*516 + row] = g_qkv[rb + 512];
    }
    __syncthreads();

    const float4* Ks4 = (const float4*)Ks;
    const float4* Vt4 = (const float4*)Vt;
    const float SCALE = 0.17677669529663687f;  // 1/sqrt(32)

    for (int it = 0; it < 16; it++) {
        int rb = (it*8 + w) * 4;
        float qe[4];
        #pragma unroll
        for (int r = 0; r < 4; r++)
            qe[r] = g_qkv[(size_t)(gbase + rb + r) * 768 + h*32 + lane];

        float s[4][16];
        #pragma unroll
        for (int r = 0; r < 4; r++)
            #pragma unroll
            for (int t = 0; t < 16; t++) s[r][t] = 0.f;

        #pragma unroll
        for (int c4 = 0; c4 < 8; c4++) {
            float qc[4][4];
            #pragma unroll
            for (int r = 0; r < 4; r++)
                #pragma unroll
                for (int cc = 0; cc < 4; cc++)
                    qc[r][cc] = __shfl_sync(0xffffffffu, qe[r], c4*4 + cc);
            #pragma unroll
            for (int t = 0; t < 16; t++) {
                float4 kv = Ks4[(t*32 + lane)*9 + c4];
                #pragma unroll
                for (int r = 0; r < 4; r++)
                    s[r][t] += qc[r][0]*kv.x + qc[r][1]*kv.y + qc[r][2]*kv.z + qc[r][3]*kv.w;
            }
        }
        float Zr[4];
        #pragma unroll
        for (int r = 0; r < 4; r++) {
            float m = -1e30f;
            #pragma unroll
            for (int t = 0; t < 16; t++) m = fmaxf(m, s[r][t]);
            #pragma unroll
            for (int o = 16; o; o >>= 1) m = fmaxf(m, __shfl_xor_sync(0xffffffffu, m, o));
            float z = 0.f;
            #pragma unroll
            for (int t = 0; t < 16; t++) { float e = __expf((s[r][t] - m) * SCALE); s[r][t] = e; z += e; }
            #pragma unroll
            for (int o = 16; o; o >>= 1) z += __shfl_xor_sync(0xffffffffu, z, o);
            Zr[r] = z;
        }
        #pragma unroll
        for (int r = 0; r < 4; r++)
            #pragma unroll
            for (int t = 0; t < 16; t++)
                Ps[w*2048 + r*512 + t*32 + lane] = s[r][t];
        __syncwarp();

        float o0 = 0.f, o1 = 0.f, o2 = 0.f, o3 = 0.f;
        const float4* Pw4 = (const float4*)&Ps[w*2048];
        #pragma unroll 4
        for (int k4 = 0; k4 < 128; k4++) {
            float4 v4 = Vt4[lane*129 + k4];
            float4 p0 = Pw4[0*128 + k4];
            float4 p1 = Pw4[1*128 + k4];
            float4 p2 = Pw4[2*128 + k4];
            float4 p3 = Pw4[3*128 + k4];
            o0 += p0.x*v4.x + p0.y*v4.y + p0.z*v4.z + p0.w*v4.w;
            o1 += p1.x*v4.x + p1.y*v4.y + p1.z*v4.z + p1.w*v4.w;
            o2 += p2.x*v4.x + p2.y*v4.y + p2.z*v4.z + p2.w*v4.w;
            o3 += p3.x*v4.x + p3.y*v4.y + p3.z*v4.z + p3.w*v4.w;
        }
        g_attno[(size_t)(gbase + rb + 0)*HD + h*32 + lane] = o0 / Zr[0];
        g_attno[(size_t)(gbase + rb + 1)*HD + h*32 + lane] = o1 / Zr[1];
        g_attno[(size_t)(gbase + rb + 2)*HD + h*32 + lane] = o2 / Zr[2];
        g_attno[(size_t)(gbase + rb + 3)*HD + h*32 + lane] = o3 / Zr[3];
        __syncwarp();
    }
}

// ----------------------------- LN2 + combine -----------------------------
__global__ void __launch_bounds__(256) k_combine(const float* __restrict__ g2, const float* __restrict__ be2,
                                                 const float* __restrict__ alpha_p)
{
    __shared__ float red[8];
    int i = blockIdx.x, j = threadIdx.x;
    float g = g_graw[i*HD + j];
    float mean = blocksum256(g, red) * (1.0f / 256.0f);
    float d = g - mean;
    float var = blocksum256(d*d, red) * (1.0f / 256.0f);
    float y = d * rsqrtf(var + 1e-5f) * g2[j] + be2[j];
    float a = 1.0f / (1.0f + __expf(-alpha_p[0]));
    g_comb[i*HD + j] = a * g_local[i*HD + j] + (1.0f - a) * y;
}

// ----------------------------- residual + LN3 -> out -----------------------------
__global__ void __launch_bounds__(256) k_final(const float* __restrict__ g3, const float* __restrict__ be3,
                                               float* __restrict__ out)
{
    __shared__ float red[8];
    int i = blockIdx.x, j = threadIdx.x;
    float v = g_comb[i*HD + j] + g_f2[i*HD + j];
    float mean = blocksum256(v, red) * (1.0f / 256.0f);
    float d = v - mean;
    float var = blocksum256(d*d, red) * (1.0f / 256.0f);
    out[i*HD + j] = d * rsqrtf(var + 1e-5f) * g3[j] + be3[j];
}

// ----------------------------- launch -----------------------------
extern "C" void kernel_launch(void* const* d_in, const int* in_sizes, int n_in,
                              void* d_out, int out_size)
{
    const float* x        = (const float*)d_in[0];
    const float* ea       = (const float*)d_in[1];
    const float* W_l      = (const float*)d_in[2];
    const float* b_l      = (const float*)d_in[3];
    const float* W_r      = (const float*)d_in[4];
    const float* b_r      = (const float*)d_in[5];
    const float* W_e      = (const float*)d_in[6];
    const float* att      = (const float*)d_in[7];
    const float* bias_gat = (const float*)d_in[8];
    const float* ipw      = (const float*)d_in[9];
    const float* ipb      = (const float*)d_in[10];
    const float* opw      = (const float*)d_in[11];
    const float* opb      = (const float*)d_in[12];
    const float* alpha    = (const float*)d_in[13];
    const float* W1       = (const float*)d_in[14];
    const float* b1       = (const float*)d_in[15];
    const float* W2       = (const float*)d_in[16];
    const float* b2       = (const float*)d_in[17];
    const float* g1       = (const float*)d_in[18];
    const float* be1      = (const float*)d_in[19];
    const float* g2       = (const float*)d_in[20];
    const float* be2      = (const float*)d_in[21];
    const float* g3       = (const float*)d_in[22];
    const float* be3      = (const float*)d_in[23];
    const int*   ei       = (const int*)d_in[24];
    float* out = (float*)d_out;

    float *xl, *xr, *qkv, *attno, *graw, *comb, *h1, *f2;
    cudaGetSymbolAddress((void**)&xl,    g_xl);
    cudaGetSymbolAddress((void**)&xr,    g_xr);
    cudaGetSymbolAddress((void**)&qkv,   g_qkv);
    cudaGetSymbolAddress((void**)&attno, g_attno);
    cudaGetSymbolAddress((void**)&graw,  g_graw);
    cudaGetSymbolAddress((void**)&comb,  g_comb);
    cudaGetSymbolAddress((void**)&h1,    g_h1);
    cudaGetSymbolAddress((void**)&f2,    g_f2);

    cudaFuncSetAttribute(k_attn, cudaFuncAttributeMaxDynamicSharedMemorySize, ATTN_SMEM_BYTES);

    dim3 g256(256, 1, 1);

    // graph prep + GAT path
    k_zero<<<(NTOT + 255)/256, 256>>>();
    k_gemm<false,false><<<dim3(HD/128, NTOT/128), 256>>>(x, W_l, b_l, xl, NTOT, HD, HD);
    k_gemm<false,false><<<dim3(HD/128, NTOT/128), 256>>>(x, W_r, b_r, xr, NTOT, HD, HD);
    k_edgecnt<<<(EDG + 255)/256, 256>>>(ei, ea);
    k_scan<<<1, 1024>>>();
    k_fill<<<(EDG + 255)/256, 256>>>(ei);
    k_gat<<<NTOT, 256>>>(ei, ea, W_e, att, bias_gat, g1, be1);

    // global attention path
    k_gemm<true,false><<<dim3(3*HD/128, NTOT/128), 256>>>(x, ipw, ipb, qkv, NTOT, 3*HD, HD);
    k_attn<<<GRAPHS*HEADS, 256, ATTN_SMEM_BYTES>>>();
    k_gemm<true,false><<<dim3(HD/128, NTOT/128), 256>>>(attno, opw, opb, graw, NTOT, HD, HD);

    // combine + FFN + final LN
    k_combine<<<NTOT, 256>>>(g2, be2, alpha);
    k_gemm<false,true ><<<dim3(4*HD/128, NTOT/128), 256>>>(comb, W1, b1, h1, NTOT, 4*HD, HD);
    k_gemm<false,false><<<dim3(HD/128, NTOT/128), 256>>>(h1, W2, b2, f2, NTOT, HD, 4*HD);
    k_final<<<NTOT, 256>>>(g3, be3, out);

    (void)in_sizes; (void)n_in; (void)out_size;
}

// round 3
// speedup vs baseline: 1.2732x; 1.2732x over previous
#include <cuda_runtime.h>
#include <math.h>

#define NTOT   32768
#define EDG    524288
#define HD     256
#define HEADS  8
#define CDIM   32
#define GRAPHS 64
#define NPG    512
#define CAP    128

// ----------------------------- scratch (static device) -----------------------------
__device__ __align__(16) float g_xl[NTOT*HD];
__device__ __align__(16) float g_xr[NTOT*HD];
__device__ __align__(16) float g_qkv[NTOT*3*HD];
__device__ __align__(16) float g_attno[NTOT*HD];
__device__ __align__(16) float g_graw[NTOT*HD];
__device__ __align__(16) float g_local[NTOT*HD];
__device__ __align__(16) float g_comb[NTOT*HD];
__device__ __align__(16) float g_h1[NTOT*4*HD];
__device__ __align__(16) float g_f2[NTOT*HD];
__device__ int   g_deg[NTOT];
__device__ int   g_off[NTOT];
__device__ int   g_cur[NTOT];
__device__ int   g_csr[EDG];
__device__ float g_easum[NTOT*2];

// ----------------------------- helpers -----------------------------
__device__ __forceinline__ unsigned tf32cvt(float f){
    unsigned r;
    asm("cvt.rna.tf32.f32 %0,%1;" : "=r"(r) : "f"(f));
    return r;
}
__device__ __forceinline__ float geluf(float x){
    return 0.5f * x * (1.0f + erff(x * 0.70710678118654752f));
}
__device__ __forceinline__ float blocksum256(float v, float* red){
    int lane = threadIdx.x & 31, wid = threadIdx.x >> 5;
    #pragma unroll
    for (int o = 16; o; o >>= 1) v += __shfl_xor_sync(0xffffffffu, v, o);
    if (lane == 0) red[wid] = v;
    __syncthreads();
    float r = (threadIdx.x < 8) ? red[threadIdx.x] : 0.0f;
    if (wid == 0) {
        #pragma unroll
        for (int o = 4; o; o >>= 1) r += __shfl_xor_sync(0xffffffffu, r, o);
        if (lane == 0) red[0] = r;
    }
    __syncthreads();
    float out = red[0];
    __syncthreads();
    return out;
}

// ----------------------------- tiny graph kernels -----------------------------
__global__ void k_zero(){
    int i = blockIdx.x * blockDim.x + threadIdx.x;
    if (i < NTOT) { g_deg[i] = 0; g_cur[i] = 0; g_easum[2*i] = 0.f; g_easum[2*i+1] = 0.f; }
}
__global__ void k_edgecnt(const int* __restrict__ ei, const float* __restrict__ ea){
    int e = blockIdx.x * blockDim.x + threadIdx.x;
    if (e < EDG) {
        int d = ei[EDG + e];
        atomicAdd(&g_deg[d], 1);
        atomicAdd(&g_easum[2*d],     ea[2*e]);
        atomicAdd(&g_easum[2*d + 1], ea[2*e + 1]);
    }
}
__global__ void k_scan(){
    __shared__ int wsum[32];
    int tid = threadIdx.x;
    int base = tid * 32;
    int loc[32]; int s = 0;
    #pragma unroll
    for (int t = 0; t < 32; t++) { loc[t] = s; s += g_deg[base + t]; }
    int lane = tid & 31, wid = tid >> 5;
    int v = s;
    #pragma unroll
    for (int o = 1; o < 32; o <<= 1) { int n = __shfl_up_sync(0xffffffffu, v, o); if (lane >= o) v += n; }
    if (lane == 31) wsum[wid] = v;
    __syncthreads();
    if (wid == 0) {
        int w = wsum[lane];
        #pragma unroll
        for (int o = 1; o < 32; o <<= 1) { int n = __shfl_up_sync(0xffffffffu, w, o); if (lane >= o) w += n; }
        wsum[lane] = w;
    }
    __syncthreads();
    int chunk_base = v - s + (wid ? wsum[wid - 1] : 0);
    #pragma unroll
    for (int t = 0; t < 32; t++) g_off[base + t] = chunk_base + loc[t];
}
__global__ void k_fill(const int* __restrict__ ei){
    int e = blockIdx.x * blockDim.x + threadIdx.x;
    if (e < EDG) {
        int d = ei[EDG + e];
        int p = atomicAdd(&g_cur[d], 1);
        g_csr[g_off[d] + p] = e;
    }
}

// ----------------------------- GATv2 per-node kernel -----------------------------
__global__ void __launch_bounds__(256) k_gat(const int* __restrict__ ei, const float* __restrict__ ea,
                                             const float* __restrict__ We, const float* __restrict__ att,
                                             const float* __restrict__ bias_gat,
                                             const float* __restrict__ g1, const float* __restrict__ be1)
{
    int i = blockIdx.x;
    int j = threadIdx.x;
    int h = j >> 5, lane = j & 31;
    __shared__ int   s_src[CAP];
    __shared__ float s_e0[CAP], s_e1[CAP];
    __shared__ float s_sc[(CAP + 1) * HEADS];
    __shared__ float s_Z[HEADS];
    __shared__ float s_red[8];

    int degr = g_deg[i];
    int deg  = degr > CAP ? CAP : degr;
    int off  = g_off[i];
    for (int k = j; k < deg; k += 256) {
        int eid = g_csr[off + k];
        s_src[k] = ei[eid];
        s_e0[k] = ea[2*eid];
        s_e1[k] = ea[2*eid + 1];
    }
    float xr_j = g_xr[i*HD + j];
    float xl_i = g_xl[i*HD + j];
    float we0 = We[j], we1 = We[HD + j];
    float attj = att[j];
    float dr = fmaxf((float)degr, 1.0f);
    float m0 = g_easum[2*i] / dr, m1 = g_easum[2*i + 1] / dr;
    __syncthreads();

    for (int k = 0; k <= deg; k++) {
        float xls, e0, e1;
        if (k < deg) { int s = s_src[k]; xls = g_xl[s*HD + j]; e0 = s_e0[k]; e1 = s_e1[k]; }
        else         { xls = xl_i; e0 = m0; e1 = m1; }
        float v = xls + xr_j + e0*we0 + e1*we1;
        v = v > 0.f ? v : 0.2f * v;
        float p = v * attj;
        #pragma unroll
        for (int o = 16; o; o >>= 1) p += __shfl_xor_sync(0xffffffffu, p, o);
        if (lane == 0) s_sc[k*HEADS + h] = p;
    }
    __syncthreads();

    if (j < HEADS) {
        float m = -1e30f;
        for (int k = 0; k <= deg; k++) m = fmaxf(m, s_sc[k*HEADS + j]);
        float Z = 0.f;
        for (int k = 0; k <= deg; k++) { float e = __expf(s_sc[k*HEADS + j] - m); s_sc[k*HEADS + j] = e; Z += e; }
        s_Z[j] = Z;
    }
    __syncthreads();

    float acc = 0.f;
    for (int k = 0; k < deg; k++) acc += s_sc[k*HEADS + h] * g_xl[s_src[k]*HD + j];
    acc += s_sc[deg*HEADS + h] * xl_i;
    float val = acc / s_Z[h] + bias_gat[j];

    float mean = blocksum256(val, s_red) * (1.0f / 256.0f);
    float d = val - mean;
    float var = blocksum256(d*d, s_red) * (1.0f / 256.0f);
    g_local[i*HD + j] = d * rsqrtf(var + 1e-5f) * g1[j] + be1[j];
}

// ----------------------------- TF32 tensor-core GEMM -----------------------------
// C[M,N] = A[M,K] * op(B) + bias (+GELU).  TB=false: B KxN row-major; TB=true: B NxK.
// 128x128 block tile, 256 threads (2x4 warps, 64x32 warp tile), K-step 16, mma.m16n8k8.tf32.
template<bool TB, bool ACT>
__global__ void __launch_bounds__(256) k_gemm_tc(const float* __restrict__ A, const float* __restrict__ B,
                                                 const float* __restrict__ bias, float* __restrict__ C,
                                                 int M, int N, int K)
{
    __shared__ unsigned As[128][18];   // [m][k] pad 2
    __shared__ unsigned Bs[16][132];   // [k][n] pad 4
    int bm = blockIdx.y * 128, bn = blockIdx.x * 128;
    int tid = threadIdx.x;
    int wid = tid >> 5, lane = tid & 31;
    int warpm = wid >> 2, warpn = wid & 3;   // 2 x 4
    int lr = lane >> 2, lc = lane & 3;

    float acc[4][4][4];
    #pragma unroll
    for (int mt = 0; mt < 4; mt++)
        #pragma unroll
        for (int nt = 0; nt < 4; nt++)
            #pragma unroll
            for (int q = 0; q < 4; q++) acc[mt][nt][q] = 0.f;

    for (int k0 = 0; k0 < K; k0 += 16) {
        // load A tile: 128x16
        #pragma unroll
        for (int t = 0; t < 2; t++) {
            int idx = tid + t*256;
            int row = idx >> 2, c4 = idx & 3;
            float4 av = *(const float4*)&A[(size_t)(bm + row)*K + k0 + c4*4];
            As[row][c4*4+0] = tf32cvt(av.x); As[row][c4*4+1] = tf32cvt(av.y);
            As[row][c4*4+2] = tf32cvt(av.z); As[row][c4*4+3] = tf32cvt(av.w);
        }
        // load B tile: 16x128 (as [k][n])
        if (!TB) {
            #pragma unroll
            for (int t = 0; t < 2; t++) {
                int idx = tid + t*256;
                int r = idx >> 5, c4 = idx & 31;
                float4 bv = *(const float4*)&B[(size_t)(k0 + r)*N + bn + c4*4];
                Bs[r][c4*4+0] = tf32cvt(bv.x); Bs[r][c4*4+1] = tf32cvt(bv.y);
                Bs[r][c4*4+2] = tf32cvt(bv.z); Bs[r][c4*4+3] = tf32cvt(bv.w);
            }
        } else {
            #pragma unroll
            for (int t = 0; t < 2; t++) {
                int idx = tid + t*256;
                int n = idx >> 2, kc = idx & 3;
                float4 bv = *(const float4*)&B[(size_t)(bn + n)*K + k0 + kc*4];
                Bs[kc*4+0][n] = tf32cvt(bv.x); Bs[kc*4+1][n] = tf32cvt(bv.y);
                Bs[kc*4+2][n] = tf32cvt(bv.z); Bs[kc*4+3][n] = tf32cvt(bv.w);
            }
        }
        __syncthreads();

        #pragma unroll
        for (int s = 0; s < 16; s += 8) {
            unsigned af[4][4], bf[4][2];
            #pragma unroll
            for (int mt = 0; mt < 4; mt++) {
                int r0 = warpm*64 + mt*16 + lr;
                af[mt][0] = As[r0    ][s + lc];
                af[mt][1] = As[r0 + 8][s + lc];
                af[mt][2] = As[r0    ][s + 4 + lc];
                af[mt][3] = As[r0 + 8][s + 4 + lc];
            }
            #pragma unroll
            for (int nt = 0; nt < 4; nt++) {
                int cn = warpn*32 + nt*8 + lr;
                bf[nt][0] = Bs[s + lc    ][cn];
                bf[nt][1] = Bs[s + 4 + lc][cn];
            }
            #pragma unroll
            for (int mt = 0; mt < 4; mt++)
                #pragma unroll
                for (int nt = 0; nt < 4; nt++) {
                    asm volatile(
                        "mma.sync.aligned.m16n8k8.row.col.f32.tf32.tf32.f32 "
                        "{%0,%1,%2,%3},{%4,%5,%6,%7},{%8,%9},{%0,%1,%2,%3};"
                        : "+f"(acc[mt][nt][0]), "+f"(acc[mt][nt][1]),
                          "+f"(acc[mt][nt][2]), "+f"(acc[mt][nt][3])
                        : "r"(af[mt][0]), "r"(af[mt][1]), "r"(af[mt][2]), "r"(af[mt][3]),
                          "r"(bf[nt][0]), "r"(bf[nt][1]));
                }
        }
        __syncthreads();
    }

    // epilogue
    #pragma unroll
    for (int mt = 0; mt < 4; mt++) {
        int r0 = bm + warpm*64 + mt*16 + lr;
        #pragma unroll
        for (int nt = 0; nt < 4; nt++) {
            int c0 = bn + warpn*32 + nt*8 + lc*2;
            float b0 = bias[c0], b1 = bias[c0+1];
            float v0 = acc[mt][nt][0] + b0, v1 = acc[mt][nt][1] + b1;
            float v2 = acc[mt][nt][2] + b0, v3 = acc[mt][nt][3] + b1;
            if (ACT) { v0 = geluf(v0); v1 = geluf(v1); v2 = geluf(v2); v3 = geluf(v3); }
            float2 o0 = { v0, v1 }, o1 = { v2, v3 };
            *(float2*)&C[(size_t)r0*N + c0]       = o0;
            *(float2*)&C[(size_t)(r0+8)*N + c0]   = o1;
        }
    }
}

// ----------------------------- fused MHA (one block per (graph, head)) -----------------------------
#define ATTN_SMEM_BYTES ((18432 + 16512 + 16384) * 4)
__global__ void __launch_bounds__(256) k_attn()
{
    extern __shared__ float sm[];
    float* Ks = sm;
    float* Vt = sm + 18432;
    float* Ps = sm + 18432 + 16512;
    int gh = blockIdx.x;
    int g = gh >> 3, h = gh & 7;
    int tid = threadIdx.x, w = tid >> 5, lane = tid & 31;
    int gbase = g * NPG;

    for (int idx = tid; idx < NPG * CDIM; idx += 256) {
        int row = idx >> 5, c = idx & 31;
        size_t rb = (size_t)(gbase + row) * 768 + h*32 + c;
        Ks[row*36 + c]  = g_qkv[rb + 256];
        Vt[c*516 + row] = g_qkv[rb + 512];
    }
    __syncthreads();

    const float4* Ks4 = (const float4*)Ks;
    const float4* Vt4 = (const float4*)Vt;
    const float SCALE = 0.17677669529663687f;

    for (int it = 0; it < 16; it++) {
        int rb = (it*8 + w) * 4;
        float qe[4];
        #pragma unroll
        for (int r = 0; r < 4; r++)
            qe[r] = g_qkv[(size_t)(gbase + rb + r) * 768 + h*32 + lane];

        float s[4][16];
        #pragma unroll
        for (int r = 0; r < 4; r++)
            #pragma unroll
            for (int t = 0; t < 16; t++) s[r][t] = 0.f;

        #pragma unroll
        for (int c4 = 0; c4 < 8; c4++) {
            float qc[4][4];
            #pragma unroll
            for (int r = 0; r < 4; r++)
                #pragma unroll
                for (int cc = 0; cc < 4; cc++)
                    qc[r][cc] = __shfl_sync(0xffffffffu, qe[r], c4*4 + cc);
            #pragma unroll
            for (int t = 0; t < 16; t++) {
                float4 kv = Ks4[(t*32 + lane)*9 + c4];
                #pragma unroll
                for (int r = 0; r < 4; r++)
                    s[r][t] += qc[r][0]*kv.x + qc[r][1]*kv.y + qc[r][2]*kv.z + qc[r][3]*kv.w;
            }
        }
        float Zr[4];
        #pragma unroll
        for (int r = 0; r < 4; r++) {
            float m = -1e30f;
            #pragma unroll
            for (int t = 0; t < 16; t++) m = fmaxf(m, s[r][t]);
            #pragma unroll
            for (int o = 16; o; o >>= 1) m = fmaxf(m, __shfl_xor_sync(0xffffffffu, m, o));
            float z = 0.f;
            #pragma unroll
            for (int t = 0; t < 16; t++) { float e = __expf((s[r][t] - m) * SCALE); s[r][t] = e; z += e; }
            #pragma unroll
            for (int o = 16; o; o >>= 1) z += __shfl_xor_sync(0xffffffffu, z, o);
            Zr[r] = z;
        }
        #pragma unroll
        for (int r = 0; r < 4; r++)
            #pragma unroll
            for (int t = 0; t < 16; t++)
                Ps[w*2048 + r*512 + t*32 + lane] = s[r][t];
        __syncwarp();

        float o0 = 0.f, o1 = 0.f, o2 = 0.f, o3 = 0.f;
        const float4* Pw4 = (const float4*)&Ps[w*2048];
        #pragma unroll 4
        for (int k4 = 0; k4 < 128; k4++) {
            float4 v4 = Vt4[lane*129 + k4];
            float4 p0 = Pw4[0*128 + k4];
            float4 p1 = Pw4[1*128 + k4];
            float4 p2 = Pw4[2*128 + k4];
            float4 p3 = Pw4[3*128 + k4];
            o0 += p0.x*v4.x + p0.y*v4.y + p0.z*v4.z + p0.w*v4.w;
            o1 += p1.x*v4.x + p1.y*v4.y + p1.z*v4.z + p1.w*v4.w;
            o2 += p2.x*v4.x + p2.y*v4.y + p2.z*v4.z + p2.w*v4.w;
            o3 += p3.x*v4.x + p3.y*v4.y + p3.z*v4.z + p3.w*v4.w;
        }
        g_attno[(size_t)(gbase + rb + 0)*HD + h*32 + lane] = o0 / Zr[0];
        g_attno[(size_t)(gbase + rb + 1)*HD + h*32 + lane] = o1 / Zr[1];
        g_attno[(size_t)(gbase + rb + 2)*HD + h*32 + lane] = o2 / Zr[2];
        g_attno[(size_t)(gbase + rb + 3)*HD + h*32 + lane] = o3 / Zr[3];
        __syncwarp();
    }
}

// ----------------------------- LN2 + combine -----------------------------
__global__ void __launch_bounds__(256) k_combine(const float* __restrict__ g2, const float* __restrict__ be2,
                                                 const float* __restrict__ alpha_p)
{
    __shared__ float red[8];
    int i = blockIdx.x, j = threadIdx.x;
    float g = g_graw[i*HD + j];
    float mean = blocksum256(g, red) * (1.0f / 256.0f);
    float d = g - mean;
    float var = blocksum256(d*d, red) * (1.0f / 256.0f);
    float y = d * rsqrtf(var + 1e-5f) * g2[j] + be2[j];
    float a = 1.0f / (1.0f + __expf(-alpha_p[0]));
    g_comb[i*HD + j] = a * g_local[i*HD + j] + (1.0f - a) * y;
}

// ----------------------------- residual + LN3 -> out -----------------------------
__global__ void __launch_bounds__(256) k_final(const float* __restrict__ g3, const float* __restrict__ be3,
                                               float* __restrict__ out)
{
    __shared__ float red[8];
    int i = blockIdx.x, j = threadIdx.x;
    float v = g_comb[i*HD + j] + g_f2[i*HD + j];
    float mean = blocksum256(v, red) * (1.0f / 256.0f);
    float d = v - mean;
    float var = blocksum256(d*d, red) * (1.0f / 256.0f);
    out[i*HD + j] = d * rsqrtf(var + 1e-5f) * g3[j] + be3[j];
}

// ----------------------------- launch -----------------------------
extern "C" void kernel_launch(void* const* d_in, const int* in_sizes, int n_in,
                              void* d_out, int out_size)
{
    const float* x        = (const float*)d_in[0];
    const float* ea       = (const float*)d_in[1];
    const float* W_l      = (const float*)d_in[2];
    const float* b_l      = (const float*)d_in[3];
    const float* W_r      = (const float*)d_in[4];
    const float* b_r      = (const float*)d_in[5];
    const float* W_e      = (const float*)d_in[6];
    const float* att      = (const float*)d_in[7];
    const float* bias_gat = (const float*)d_in[8];
    const float* ipw      = (const float*)d_in[9];
    const float* ipb      = (const float*)d_in[10];
    const float* opw      = (const float*)d_in[11];
    const float* opb      = (const float*)d_in[12];
    const float* alpha    = (const float*)d_in[13];
    const float* W1       = (const float*)d_in[14];
    const float* b1       = (const float*)d_in[15];
    const float* W2       = (const float*)d_in[16];
    const float* b2       = (const float*)d_in[17];
    const float* g1       = (const float*)d_in[18];
    const float* be1      = (const float*)d_in[19];
    const float* g2       = (const float*)d_in[20];
    const float* be2      = (const float*)d_in[21];
    const float* g3       = (const float*)d_in[22];
    const float* be3      = (const float*)d_in[23];
    const int*   ei       = (const int*)d_in[24];
    float* out = (float*)d_out;

    float *xl, *xr, *qkv, *attno, *graw, *comb, *h1, *f2;
    cudaGetSymbolAddress((void**)&xl,    g_xl);
    cudaGetSymbolAddress((void**)&xr,    g_xr);
    cudaGetSymbolAddress((void**)&qkv,   g_qkv);
    cudaGetSymbolAddress((void**)&attno, g_attno);
    cudaGetSymbolAddress((void**)&graw,  g_graw);
    cudaGetSymbolAddress((void**)&comb,  g_comb);
    cudaGetSymbolAddress((void**)&h1,    g_h1);
    cudaGetSymbolAddress((void**)&f2,    g_f2);

    cudaFuncSetAttribute(k_attn, cudaFuncAttributeMaxDynamicSharedMemorySize, ATTN_SMEM_BYTES);

    // graph prep + GAT path
    k_zero<<<(NTOT + 255)/256, 256>>>();
    k_gemm_tc<false,false><<<dim3(HD/128, NTOT/128), 256>>>(x, W_l, b_l, xl, NTOT, HD, HD);
    k_gemm_tc<false,false><<<dim3(HD/128, NTOT/128), 256>>>(x, W_r, b_r, xr, NTOT, HD, HD);
    k_edgecnt<<<(EDG + 255)/256, 256>>>(ei, ea);
    k_scan<<<1, 1024>>>();
    k_fill<<<(EDG + 255)/256, 256>>>(ei);
    k_gat<<<NTOT, 256>>>(ei, ea, W_e, att, bias_gat, g1, be1);

    // global attention path
    k_gemm_tc<true,false><<<dim3(3*HD/128, NTOT/128), 256>>>(x, ipw, ipb, qkv, NTOT, 3*HD, HD);
    k_attn<<<GRAPHS*HEADS, 256, ATTN_SMEM_BYTES>>>();
    k_gemm_tc<true,false><<<dim3(HD/128, NTOT/128), 256>>>(attno, opw, opb, graw, NTOT, HD, HD);

    // combine + FFN + final LN
    k_combine<<<NTOT, 256>>>(g2, be2, alpha);
    k_gemm_tc<false,true ><<<dim3(4*HD/128, NTOT/128), 256>>>(comb, W1, b1, h1, NTOT, 4*HD, HD);
    k_gemm_tc<false,false><<<dim3(HD/128, NTOT/128), 256>>>(h1, W2, b2, f2, NTOT, HD, 4*HD);
    k_final<<<NTOT, 256>>>(g3, be3, out);

    (void)in_sizes; (void)n_in; (void)out_size;
}

// round 4
// speedup vs baseline: 1.7524x; 1.3764x over previous
#include <cuda_runtime.h>
#include <math.h>

#define NTOT   32768
#define EDG    524288
#define HD     256
#define HEADS  8
#define CDIM   32
#define GRAPHS 64
#define NPG    512
#define CAP    128

// ----------------------------- scratch (static device) -----------------------------
__device__ __align__(16) float g_xl[NTOT*HD];
__device__ __align__(16) float g_xr[NTOT*HD];
__device__ __align__(16) float g_qkv[NTOT*3*HD];
__device__ __align__(16) float g_attno[NTOT*HD];
__device__ __align__(16) float g_graw[NTOT*HD];
__device__ __align__(16) float g_local[NTOT*HD];
__device__ __align__(16) float g_comb[NTOT*HD];
__device__ __align__(16) float g_h1[NTOT*4*HD];
__device__ __align__(16) float g_f2[NTOT*HD];
__device__ int   g_deg[NTOT];
__device__ int   g_off[NTOT];
__device__ int   g_cur[NTOT];
__device__ int   g_csr[EDG];
__device__ float g_easum[NTOT*2];

// ----------------------------- helpers -----------------------------
__device__ __forceinline__ unsigned tf32cvt(float f){
    unsigned r;
    asm("cvt.rna.tf32.f32 %0,%1;" : "=r"(r) : "f"(f));
    return r;
}
__device__ __forceinline__ void mma_tf32(float* c, const unsigned* a, unsigned b0, unsigned b1){
    asm volatile(
        "mma.sync.aligned.m16n8k8.row.col.f32.tf32.tf32.f32 "
        "{%0,%1,%2,%3},{%4,%5,%6,%7},{%8,%9},{%0,%1,%2,%3};"
        : "+f"(c[0]), "+f"(c[1]), "+f"(c[2]), "+f"(c[3])
        : "r"(a[0]), "r"(a[1]), "r"(a[2]), "r"(a[3]), "r"(b0), "r"(b1));
}
__device__ __forceinline__ float geluf(float x){
    return 0.5f * x * (1.0f + erff(x * 0.70710678118654752f));
}
__device__ __forceinline__ float blocksum256(float v, float* red){
    int lane = threadIdx.x & 31, wid = threadIdx.x >> 5;
    #pragma unroll
    for (int o = 16; o; o >>= 1) v += __shfl_xor_sync(0xffffffffu, v, o);
    if (lane == 0) red[wid] = v;
    __syncthreads();
    float r = (threadIdx.x < 8) ? red[threadIdx.x] : 0.0f;
    if (wid == 0) {
        #pragma unroll
        for (int o = 4; o; o >>= 1) r += __shfl_xor_sync(0xffffffffu, r, o);
        if (lane == 0) red[0] = r;
    }
    __syncthreads();
    float out = red[0];
    __syncthreads();
    return out;
}

// ----------------------------- tiny graph kernels -----------------------------
__global__ void k_zero(){
    int i = blockIdx.x * blockDim.x + threadIdx.x;
    if (i < NTOT) { g_deg[i] = 0; g_cur[i] = 0; g_easum[2*i] = 0.f; g_easum[2*i+1] = 0.f; }
}
__global__ void k_edgecnt(const int* __restrict__ ei, const float* __restrict__ ea){
    int e = blockIdx.x * blockDim.x + threadIdx.x;
    if (e < EDG) {
        int d = ei[EDG + e];
        atomicAdd(&g_deg[d], 1);
        atomicAdd(&g_easum[2*d],     ea[2*e]);
        atomicAdd(&g_easum[2*d + 1], ea[2*e + 1]);
    }
}
__global__ void k_scan(){
    __shared__ int wsum[32];
    int tid = threadIdx.x;
    int base = tid * 32;
    int loc[32]; int s = 0;
    #pragma unroll
    for (int t = 0; t < 32; t++) { loc[t] = s; s += g_deg[base + t]; }
    int lane = tid & 31, wid = tid >> 5;
    int v = s;
    #pragma unroll
    for (int o = 1; o < 32; o <<= 1) { int n = __shfl_up_sync(0xffffffffu, v, o); if (lane >= o) v += n; }
    if (lane == 31) wsum[wid] = v;
    __syncthreads();
    if (wid == 0) {
        int w = wsum[lane];
        #pragma unroll
        for (int o = 1; o < 32; o <<= 1) { int n = __shfl_up_sync(0xffffffffu, w, o); if (lane >= o) w += n; }
        wsum[lane] = w;
    }
    __syncthreads();
    int chunk_base = v - s + (wid ? wsum[wid - 1] : 0);
    #pragma unroll
    for (int t = 0; t < 32; t++) g_off[base + t] = chunk_base + loc[t];
}
__global__ void k_fill(const int* __restrict__ ei){
    int e = blockIdx.x * blockDim.x + threadIdx.x;
    if (e < EDG) {
        int d = ei[EDG + e];
        int p = atomicAdd(&g_cur[d], 1);
        g_csr[g_off[d] + p] = e;
    }
}

// ----------------------------- GATv2 per-node kernel -----------------------------
__global__ void __launch_bounds__(256) k_gat(const int* __restrict__ ei, const float* __restrict__ ea,
                                             const float* __restrict__ We, const float* __restrict__ att,
                                             const float* __restrict__ bias_gat,
                                             const float* __restrict__ g1, const float* __restrict__ be1)
{
    int i = blockIdx.x;
    int j = threadIdx.x;
    int h = j >> 5, lane = j & 31;
    __shared__ int   s_src[CAP];
    __shared__ float s_e0[CAP], s_e1[CAP];
    __shared__ float s_sc[(CAP + 1) * HEADS];
    __shared__ float s_Z[HEADS];
    __shared__ float s_red[8];

    int degr = g_deg[i];
    int deg  = degr > CAP ? CAP : degr;
    int off  = g_off[i];
    for (int k = j; k < deg; k += 256) {
        int eid = g_csr[off + k];
        s_src[k] = ei[eid];
        s_e0[k] = ea[2*eid];
        s_e1[k] = ea[2*eid + 1];
    }
    float xr_j = g_xr[i*HD + j];
    float xl_i = g_xl[i*HD + j];
    float we0 = We[j], we1 = We[HD + j];
    float attj = att[j];
    float dr = fmaxf((float)degr, 1.0f);
    float m0 = g_easum[2*i] / dr, m1 = g_easum[2*i + 1] / dr;
    __syncthreads();

    for (int k = 0; k <= deg; k++) {
        float xls, e0, e1;
        if (k < deg) { int s = s_src[k]; xls = g_xl[s*HD + j]; e0 = s_e0[k]; e1 = s_e1[k]; }
        else         { xls = xl_i; e0 = m0; e1 = m1; }
        float v = xls + xr_j + e0*we0 + e1*we1;
        v = v > 0.f ? v : 0.2f * v;
        float p = v * attj;
        #pragma unroll
        for (int o = 16; o; o >>= 1) p += __shfl_xor_sync(0xffffffffu, p, o);
        if (lane == 0) s_sc[k*HEADS + h] = p;
    }
    __syncthreads();

    if (j < HEADS) {
        float m = -1e30f;
        for (int k = 0; k <= deg; k++) m = fmaxf(m, s_sc[k*HEADS + j]);
        float Z = 0.f;
        for (int k = 0; k <= deg; k++) { float e = __expf(s_sc[k*HEADS + j] - m); s_sc[k*HEADS + j] = e; Z += e; }
        s_Z[j] = Z;
    }
    __syncthreads();

    float acc = 0.f;
    for (int k = 0; k < deg; k++) acc += s_sc[k*HEADS + h] * g_xl[s_src[k]*HD + j];
    acc += s_sc[deg*HEADS + h] * xl_i;
    float val = acc / s_Z[h] + bias_gat[j];

    float mean = blocksum256(val, s_red) * (1.0f / 256.0f);
    float d = val - mean;
    float var = blocksum256(d*d, s_red) * (1.0f / 256.0f);
    g_local[i*HD + j] = d * rsqrtf(var + 1e-5f) * g1[j] + be1[j];
}

// ----------------------------- TF32 tensor-core GEMM -----------------------------
template<bool TB, bool ACT>
__global__ void __launch_bounds__(256) k_gemm_tc(const float* __restrict__ A, const float* __restrict__ B,
                                                 const float* __restrict__ bias, float* __restrict__ C,
                                                 int M, int N, int K)
{
    __shared__ unsigned As[128][18];
    __shared__ unsigned Bs[16][132];
    int bm = blockIdx.y * 128, bn = blockIdx.x * 128;
    int tid = threadIdx.x;
    int wid = tid >> 5, lane = tid & 31;
    int warpm = wid >> 2, warpn = wid & 3;
    int lr = lane >> 2, lc = lane & 3;

    float acc[4][4][4];
    #pragma unroll
    for (int mt = 0; mt < 4; mt++)
        #pragma unroll
        for (int nt = 0; nt < 4; nt++)
            #pragma unroll
            for (int q = 0; q < 4; q++) acc[mt][nt][q] = 0.f;

    for (int k0 = 0; k0 < K; k0 += 16) {
        #pragma unroll
        for (int t = 0; t < 2; t++) {
            int idx = tid + t*256;
            int row = idx >> 2, c4 = idx & 3;
            float4 av = *(const float4*)&A[(size_t)(bm + row)*K + k0 + c4*4];
            As[row][c4*4+0] = tf32cvt(av.x); As[row][c4*4+1] = tf32cvt(av.y);
            As[row][c4*4+2] = tf32cvt(av.z); As[row][c4*4+3] = tf32cvt(av.w);
        }
        if (!TB) {
            #pragma unroll
            for (int t = 0; t < 2; t++) {
                int idx = tid + t*256;
                int r = idx >> 5, c4 = idx & 31;
                float4 bv = *(const float4*)&B[(size_t)(k0 + r)*N + bn + c4*4];
                Bs[r][c4*4+0] = tf32cvt(bv.x); Bs[r][c4*4+1] = tf32cvt(bv.y);
                Bs[r][c4*4+2] = tf32cvt(bv.z); Bs[r][c4*4+3] = tf32cvt(bv.w);
            }
        } else {
            #pragma unroll
            for (int t = 0; t < 2; t++) {
                int idx = tid + t*256;
                int n = idx >> 2, kc = idx & 3;
                float4 bv = *(const float4*)&B[(size_t)(bn + n)*K + k0 + kc*4];
                Bs[kc*4+0][n] = tf32cvt(bv.x); Bs[kc*4+1][n] = tf32cvt(bv.y);
                Bs[kc*4+2][n] = tf32cvt(bv.z); Bs[kc*4+3][n] = tf32cvt(bv.w);
            }
        }
        __syncthreads();

        #pragma unroll
        for (int s = 0; s < 16; s += 8) {
            unsigned af[4][4], bf[4][2];
            #pragma unroll
            for (int mt = 0; mt < 4; mt++) {
                int r0 = warpm*64 + mt*16 + lr;
                af[mt][0] = As[r0    ][s + lc];
                af[mt][1] = As[r0 + 8][s + lc];
                af[mt][2] = As[r0    ][s + 4 + lc];
                af[mt][3] = As[r0 + 8][s + 4 + lc];
            }
            #pragma unroll
            for (int nt = 0; nt < 4; nt++) {
                int cn = warpn*32 + nt*8 + lr;
                bf[nt][0] = Bs[s + lc    ][cn];
                bf[nt][1] = Bs[s + 4 + lc][cn];
            }
            #pragma unroll
            for (int mt = 0; mt < 4; mt++)
                #pragma unroll
                for (int nt = 0; nt < 4; nt++)
                    mma_tf32(acc[mt][nt], af[mt], bf[nt][0], bf[nt][1]);
        }
        __syncthreads();
    }

    #pragma unroll
    for (int mt = 0; mt < 4; mt++) {
        int r0 = bm + warpm*64 + mt*16 + lr;
        #pragma unroll
        for (int nt = 0; nt < 4; nt++) {
            int c0 = bn + warpn*32 + nt*8 + lc*2;
            float b0 = bias[c0], b1 = bias[c0+1];
            float v0 = acc[mt][nt][0] + b0, v1 = acc[mt][nt][1] + b1;
            float v2 = acc[mt][nt][2] + b0, v3 = acc[mt][nt][3] + b1;
            if (ACT) { v0 = geluf(v0); v1 = geluf(v1); v2 = geluf(v2); v3 = geluf(v3); }
            float2 o0 = { v0, v1 }, o1 = { v2, v3 };
            *(float2*)&C[(size_t)r0*N + c0]       = o0;
            *(float2*)&C[(size_t)(r0+8)*N + c0]   = o1;
        }
    }
}

// ----------------------------- TF32 flash attention -----------------------------
// grid = GRAPHS*HEADS*2 blocks; block handles 256 query rows (2 tiles of 128).
// smem floats: Ks 512*36=18432 | Vt 32*516=16512 | Qs 128*36=4608 | Ps 128*132=16896
#define ATTN_SMEM_BYTES ((18432 + 16512 + 4608 + 16896) * 4)
__global__ void __launch_bounds__(256) k_attn()
{
    extern __shared__ unsigned smu[];
    unsigned* Ks = smu;
    unsigned* Vt = smu + 18432;
    unsigned* Qs = smu + 18432 + 16512;
    unsigned* Ps = smu + 18432 + 16512 + 4608;

    int blk = blockIdx.x;
    int gh = blk >> 1, half = blk & 1;
    int g = gh >> 3, h = gh & 7;
    int tid = threadIdx.x, w = tid >> 5, lane = tid & 31;
    int lr = lane >> 2, lc = lane & 3;
    int gbase = g * NPG;
    const float SCALE = 0.17677669529663687f;  // 1/sqrt(32)

    // load K (tf32, stride 36) and V^T (tf32, stride 516)
    for (int idx = tid; idx < NPG * CDIM; idx += 256) {
        int row = idx >> 5, c = idx & 31;
        size_t rb = (size_t)(gbase + row) * 768 + h*32 + c;
        Ks[row*36 + c]  = tf32cvt(g_qkv[rb + 256]);
        Vt[c*516 + row] = tf32cvt(g_qkv[rb + 512]);
    }
    __syncthreads();

    for (int qt = 0; qt < 2; qt++) {
        int qrow0 = half*256 + qt*128;
        // warp loads its 16 Q rows (warp-private smem region)
        #pragma unroll
        for (int rr = 0; rr < 16; rr++) {
            int r = w*16 + rr;
            Qs[r*36 + lane] = tf32cvt(g_qkv[(size_t)(gbase + qrow0 + r)*768 + h*32 + lane]);
        }
        __syncwarp();
        unsigned aq[4][4];
        #pragma unroll
        for (int s = 0; s < 4; s++) {
            int rb0 = w*16 + lr;
            aq[s][0] = Qs[rb0*36 + s*8 + lc];
            aq[s][1] = Qs[(rb0+8)*36 + s*8 + lc];
            aq[s][2] = Qs[rb0*36 + s*8 + 4 + lc];
            aq[s][3] = Qs[(rb0+8)*36 + s*8 + 4 + lc];
        }

        float m0 = -1e30f, m1 = -1e30f, l0 = 0.f, l1 = 0.f;
        float oacc[4][4];
        #pragma unroll
        for (int nt = 0; nt < 4; nt++)
            #pragma unroll
            for (int q = 0; q < 4; q++) oacc[nt][q] = 0.f;

        for (int j = 0; j < 4; j++) {
            int jb = j*128;
            float sacc[16][4];
            #pragma unroll
            for (int nt = 0; nt < 16; nt++)
                #pragma unroll
                for (int q = 0; q < 4; q++) sacc[nt][q] = 0.f;

            // S = Q @ K^T (chunk of 128 keys)
            #pragma unroll
            for (int nt = 0; nt < 16; nt++) {
                int kr = (jb + nt*8 + lr)*36;
                #pragma unroll
                for (int s = 0; s < 4; s++) {
                    unsigned b0 = Ks[kr + s*8 + lc];
                    unsigned b1 = Ks[kr + s*8 + 4 + lc];
                    mma_tf32(sacc[nt], aq[s], b0, b1);
                }
            }

            // chunk row max (rows lr -> c0/c1, lr+8 -> c2/c3)
            float cm0 = -1e30f, cm1 = -1e30f;
            #pragma unroll
            for (int nt = 0; nt < 16; nt++) {
                cm0 = fmaxf(cm0, fmaxf(sacc[nt][0], sacc[nt][1]));
                cm1 = fmaxf(cm1, fmaxf(sacc[nt][2], sacc[nt][3]));
            }
            cm0 = fmaxf(cm0, __shfl_xor_sync(0xffffffffu, cm0, 1));
            cm0 = fmaxf(cm0, __shfl_xor_sync(0xffffffffu, cm0, 2));
            cm1 = fmaxf(cm1, __shfl_xor_sync(0xffffffffu, cm1, 1));
            cm1 = fmaxf(cm1, __shfl_xor_sync(0xffffffffu, cm1, 2));

            float nm0 = fmaxf(m0, cm0), nm1 = fmaxf(m1, cm1);
            float sc0 = __expf((m0 - nm0) * SCALE), sc1 = __expf((m1 - nm1) * SCALE);
            m0 = nm0; m1 = nm1;

            // exp -> P (warp-private smem), accumulate row sums
            float ps0 = 0.f, ps1 = 0.f;
            int pr0 = (w*16 + lr)*132, pr1 = (w*16 + lr + 8)*132;
            #pragma unroll
            for (int nt = 0; nt < 16; nt++) {
                float p0 = __expf((sacc[nt][0] - nm0) * SCALE);
                float p1 = __expf((sacc[nt][1] - nm0) * SCALE);
                float p2 = __expf((sacc[nt][2] - nm1) * SCALE);
                float p3 = __expf((sacc[nt][3] - nm1) * SCALE);
                ps0 += p0 + p1; ps1 += p2 + p3;
                int cc = nt*8 + 2*lc;
                Ps[pr0 + cc]     = tf32cvt(p0);
                Ps[pr0 + cc + 1] = tf32cvt(p1);
                Ps[pr1 + cc]     = tf32cvt(p2);
                Ps[pr1 + cc + 1] = tf32cvt(p3);
            }
            ps0 += __shfl_xor_sync(0xffffffffu, ps0, 1);
            ps0 += __shfl_xor_sync(0xffffffffu, ps0, 2);
            ps1 += __shfl_xor_sync(0xffffffffu, ps1, 1);
            ps1 += __shfl_xor_sync(0xffffffffu, ps1, 2);
            l0 = l0 * sc0 + ps0;
            l1 = l1 * sc1 + ps1;
            #pragma unroll
            for (int nt = 0; nt < 4; nt++) {
                oacc[nt][0] *= sc0; oacc[nt][1] *= sc0;
                oacc[nt][2] *= sc1; oacc[nt][3] *= sc1;
            }
            __syncwarp();

            // O += P @ V (chunk)
            #pragma unroll
            for (int s2 = 0; s2 < 16; s2++) {
                unsigned ap[4];
                int pb0 = (w*16 + lr)*132 + s2*8;
                int pb1 = (w*16 + lr + 8)*132 + s2*8;
                ap[0] = Ps[pb0 + lc];     ap[1] = Ps[pb1 + lc];
                ap[2] = Ps[pb0 + 4 + lc]; ap[3] = Ps[pb1 + 4 + lc];
                #pragma unroll
                for (int nt2 = 0; nt2 < 4; nt2++) {
                    int vb = (nt2*8 + lr)*516 + jb + s2*8;
                    mma_tf32(oacc[nt2], ap, Vt[vb + lc], Vt[vb + 4 + lc]);
                }
            }
            __syncwarp();
        }

        float inv0 = 1.0f / l0, inv1 = 1.0f / l1;
        int row0 = gbase + qrow0 + w*16 + lr;
        #pragma unroll
        for (int nt2 = 0; nt2 < 4; nt2++) {
            int col = h*32 + nt2*8 + 2*lc;
            float2 o0 = { oacc[nt2][0]*inv0, oacc[nt2][1]*inv0 };
            float2 o1 = { oacc[nt2][2]*inv1, oacc[nt2][3]*inv1 };
            *(float2*)&g_attno[(size_t)row0*HD + col]       = o0;
            *(float2*)&g_attno[(size_t)(row0+8)*HD + col]   = o1;
        }
        __syncwarp();
    }
}

// ----------------------------- LN2 + combine -----------------------------
__global__ void __launch_bounds__(256) k_combine(const float* __restrict__ g2, const float* __restrict__ be2,
                                                 const float* __restrict__ alpha_p)
{
    __shared__ float red[8];
    int i = blockIdx.x, j = threadIdx.x;
    float g = g_graw[i*HD + j];
    float mean = blocksum256(g, red) * (1.0f / 256.0f);
    float d = g - mean;
    float var = blocksum256(d*d, red) * (1.0f / 256.0f);
    float y = d * rsqrtf(var + 1e-5f) * g2[j] + be2[j];
    float a = 1.0f / (1.0f + __expf(-alpha_p[0]));
    g_comb[i*HD + j] = a * g_local[i*HD + j] + (1.0f - a) * y;
}

// ----------------------------- residual + LN3 -> out -----------------------------
__global__ void __launch_bounds__(256) k_final(const float* __restrict__ g3, const float* __restrict__ be3,
                                               float* __restrict__ out)
{
    __shared__ float red[8];
    int i = blockIdx.x, j = threadIdx.x;
    float v = g_comb[i*HD + j] + g_f2[i*HD + j];
    float mean = blocksum256(v, red) * (1.0f / 256.0f);
    float d = v - mean;
    float var = blocksum256(d*d, red) * (1.0f / 256.0f);
    out[i*HD + j] = d * rsqrtf(var + 1e-5f) * g3[j] + be3[j];
}

// ----------------------------- launch -----------------------------
extern "C" void kernel_launch(void* const* d_in, const int* in_sizes, int n_in,
                              void* d_out, int out_size)
{
    const float* x        = (const float*)d_in[0];
    const float* ea       = (const float*)d_in[1];
    const float* W_l      = (const float*)d_in[2];
    const float* b_l      = (const float*)d_in[3];
    const float* W_r      = (const float*)d_in[4];
    const float* b_r      = (const float*)d_in[5];
    const float* W_e      = (const float*)d_in[6];
    const float* att      = (const float*)d_in[7];
    const float* bias_gat = (const float*)d_in[8];
    const float* ipw      = (const float*)d_in[9];
    const float* ipb      = (const float*)d_in[10];
    const float* opw      = (const float*)d_in[11];
    const float* opb      = (const float*)d_in[12];
    const float* alpha    = (const float*)d_in[13];
    const float* W1       = (const float*)d_in[14];
    const float* b1       = (const float*)d_in[15];
    const float* W2       = (const float*)d_in[16];
    const float* b2       = (const float*)d_in[17];
    const float* g1       = (const float*)d_in[18];
    const float* be1      = (const float*)d_in[19];
    const float* g2       = (const float*)d_in[20];
    const float* be2      = (const float*)d_in[21];
    const float* g3       = (const float*)d_in[22];
    const float* be3      = (const float*)d_in[23];
    const int*   ei       = (const int*)d_in[24];
    float* out = (float*)d_out;

    float *xl, *xr, *qkv, *attno, *graw, *comb, *h1, *f2;
    cudaGetSymbolAddress((void**)&xl,    g_xl);
    cudaGetSymbolAddress((void**)&xr,    g_xr);
    cudaGetSymbolAddress((void**)&qkv,   g_qkv);
    cudaGetSymbolAddress((void**)&attno, g_attno);
    cudaGetSymbolAddress((void**)&graw,  g_graw);
    cudaGetSymbolAddress((void**)&comb,  g_comb);
    cudaGetSymbolAddress((void**)&h1,    g_h1);
    cudaGetSymbolAddress((void**)&f2,    g_f2);

    cudaFuncSetAttribute(k_attn, cudaFuncAttributeMaxDynamicSharedMemorySize, ATTN_SMEM_BYTES);

    // graph prep + GAT path
    k_zero<<<(NTOT + 255)/256, 256>>>();
    k_gemm_tc<false,false><<<dim3(HD/128, NTOT/128), 256>>>(x, W_l, b_l, xl, NTOT, HD, HD);
    k_gemm_tc<false,false><<<dim3(HD/128, NTOT/128), 256>>>(x, W_r, b_r, xr, NTOT, HD, HD);
    k_edgecnt<<<(EDG + 255)/256, 256>>>(ei, ea);
    k_scan<<<1, 1024>>>();
    k_fill<<<(EDG + 255)/256, 256>>>(ei);
    k_gat<<<NTOT, 256>>>(ei, ea, W_e, att, bias_gat, g1, be1);

    // global attention path
    k_gemm_tc<true,false><<<dim3(3*HD/128, NTOT/128), 256>>>(x, ipw, ipb, qkv, NTOT, 3*HD, HD);
    k_attn<<<GRAPHS*HEADS*2, 256, ATTN_SMEM_BYTES>>>();
    k_gemm_tc<true,false><<<dim3(HD/128, NTOT/128), 256>>>(attno, opw, opb, graw, NTOT, HD, HD);

    // combine + FFN + final LN
    k_combine<<<NTOT, 256>>>(g2, be2, alpha);
    k_gemm_tc<false,true ><<<dim3(4*HD/128, NTOT/128), 256>>>(comb, W1, b1, h1, NTOT, 4*HD, HD);
    k_gemm_tc<false,false><<<dim3(HD/128, NTOT/128), 256>>>(h1, W2, b2, f2, NTOT, HD, 4*HD);
    k_final<<<NTOT, 256>>>(g3, be3, out);

    (void)in_sizes; (void)n_in; (void)out_size;
}

// round 5
// speedup vs baseline: 1.8793x; 1.0724x over previous
#include <cuda_runtime.h>
#include <math.h>

#define NTOT   32768
#define EDG    524288
#define HD     256
#define HEADS  8
#define CDIM   32
#define GRAPHS 64
#define NPG    512
#define CAP    128

// ----------------------------- scratch (static device) -----------------------------
__device__ __align__(16) float g_xl[NTOT*HD];
__device__ __align__(16) float g_xr[NTOT*HD];
__device__ __align__(16) float g_qkv[NTOT*3*HD];
__device__ __align__(16) float g_attno[NTOT*HD];
__device__ __align__(16) float g_graw[NTOT*HD];
__device__ __align__(16) float g_local[NTOT*HD];
__device__ __align__(16) float g_comb[NTOT*HD];
__device__ __align__(16) float g_h1[NTOT*4*HD];
__device__ __align__(16) float g_f2[NTOT*HD];
__device__ int   g_deg[NTOT];
__device__ int   g_off[NTOT];
__device__ int   g_cur[NTOT];
__device__ int   g_csr[EDG];
__device__ float g_easum[NTOT*2];

// ----------------------------- helpers -----------------------------
__device__ __forceinline__ unsigned tf32cvt(float f){
    unsigned r;
    asm("cvt.rna.tf32.f32 %0,%1;" : "=r"(r) : "f"(f));
    return r;
}
__device__ __forceinline__ void mma_tf32(float* c, const unsigned* a, unsigned b0, unsigned b1){
    asm volatile(
        "mma.sync.aligned.m16n8k8.row.col.f32.tf32.tf32.f32 "
        "{%0,%1,%2,%3},{%4,%5,%6,%7},{%8,%9},{%0,%1,%2,%3};"
        : "+f"(c[0]), "+f"(c[1]), "+f"(c[2]), "+f"(c[3])
        : "r"(a[0]), "r"(a[1]), "r"(a[2]), "r"(a[3]), "r"(b0), "r"(b1));
}
__device__ __forceinline__ float geluf(float x){
    return 0.5f * x * (1.0f + erff(x * 0.70710678118654752f));
}
__device__ __forceinline__ float blocksum256(float v, float* red){
    int lane = threadIdx.x & 31, wid = threadIdx.x >> 5;
    #pragma unroll
    for (int o = 16; o; o >>= 1) v += __shfl_xor_sync(0xffffffffu, v, o);
    if (lane == 0) red[wid] = v;
    __syncthreads();
    float r = (threadIdx.x < 8) ? red[threadIdx.x] : 0.0f;
    if (wid == 0) {
        #pragma unroll
        for (int o = 4; o; o >>= 1) r += __shfl_xor_sync(0xffffffffu, r, o);
        if (lane == 0) red[0] = r;
    }
    __syncthreads();
    float out = red[0];
    __syncthreads();
    return out;
}

// ----------------------------- tiny graph kernels -----------------------------
__global__ void k_zero(){
    int i = blockIdx.x * blockDim.x + threadIdx.x;
    if (i < NTOT) { g_deg[i] = 0; g_cur[i] = 0; g_easum[2*i] = 0.f; g_easum[2*i+1] = 0.f; }
}
__global__ void k_edgecnt(const int* __restrict__ ei, const float* __restrict__ ea){
    int e = blockIdx.x * blockDim.x + threadIdx.x;
    if (e < EDG) {
        int d = ei[EDG + e];
        atomicAdd(&g_deg[d], 1);
        atomicAdd(&g_easum[2*d],     ea[2*e]);
        atomicAdd(&g_easum[2*d + 1], ea[2*e + 1]);
    }
}
__global__ void k_scan(){
    __shared__ int wsum[32];
    int tid = threadIdx.x;
    int base = tid * 32;
    int loc[32]; int s = 0;
    #pragma unroll
    for (int t = 0; t < 32; t++) { loc[t] = s; s += g_deg[base + t]; }
    int lane = tid & 31, wid = tid >> 5;
    int v = s;
    #pragma unroll
    for (int o = 1; o < 32; o <<= 1) { int n = __shfl_up_sync(0xffffffffu, v, o); if (lane >= o) v += n; }
    if (lane == 31) wsum[wid] = v;
    __syncthreads();
    if (wid == 0) {
        int w = wsum[lane];
        #pragma unroll
        for (int o = 1; o < 32; o <<= 1) { int n = __shfl_up_sync(0xffffffffu, w, o); if (lane >= o) w += n; }
        wsum[lane] = w;
    }
    __syncthreads();
    int chunk_base = v - s + (wid ? wsum[wid - 1] : 0);
    #pragma unroll
    for (int t = 0; t < 32; t++) g_off[base + t] = chunk_base + loc[t];
}
__global__ void k_fill(const int* __restrict__ ei){
    int e = blockIdx.x * blockDim.x + threadIdx.x;
    if (e < EDG) {
        int d = ei[EDG + e];
        int p = atomicAdd(&g_cur[d], 1);
        g_csr[g_off[d] + p] = e;
    }
}

// ----------------------------- GATv2 per-node kernel -----------------------------
__global__ void __launch_bounds__(256) k_gat(const int* __restrict__ ei, const float* __restrict__ ea,
                                             const float* __restrict__ We, const float* __restrict__ att,
                                             const float* __restrict__ bias_gat,
                                             const float* __restrict__ g1, const float* __restrict__ be1)
{
    int i = blockIdx.x;
    int j = threadIdx.x;
    int h = j >> 5, lane = j & 31;
    __shared__ int   s_src[CAP];
    __shared__ float s_e0[CAP], s_e1[CAP];
    __shared__ float s_sc[(CAP + 1) * HEADS];
    __shared__ float s_Z[HEADS];
    __shared__ float s_red[8];

    int degr = g_deg[i];
    int deg  = degr > CAP ? CAP : degr;
    int off  = g_off[i];
    for (int k = j; k < deg; k += 256) {
        int eid = g_csr[off + k];
        s_src[k] = ei[eid];
        s_e0[k] = ea[2*eid];
        s_e1[k] = ea[2*eid + 1];
    }
    float xr_j = g_xr[i*HD + j];
    float xl_i = g_xl[i*HD + j];
    float we0 = We[j], we1 = We[HD + j];
    float attj = att[j];
    float dr = fmaxf((float)degr, 1.0f);
    float m0 = g_easum[2*i] / dr, m1 = g_easum[2*i + 1] / dr;
    __syncthreads();

    for (int k = 0; k <= deg; k++) {
        float xls, e0, e1;
        if (k < deg) { int s = s_src[k]; xls = g_xl[s*HD + j]; e0 = s_e0[k]; e1 = s_e1[k]; }
        else         { xls = xl_i; e0 = m0; e1 = m1; }
        float v = xls + xr_j + e0*we0 + e1*we1;
        v = v > 0.f ? v : 0.2f * v;
        float p = v * attj;
        #pragma unroll
        for (int o = 16; o; o >>= 1) p += __shfl_xor_sync(0xffffffffu, p, o);
        if (lane == 0) s_sc[k*HEADS + h] = p;
    }
    __syncthreads();

    if (j < HEADS) {
        float m = -1e30f;
        for (int k = 0; k <= deg; k++) m = fmaxf(m, s_sc[k*HEADS + j]);
        float Z = 0.f;
        for (int k = 0; k <= deg; k++) { float e = __expf(s_sc[k*HEADS + j] - m); s_sc[k*HEADS + j] = e; Z += e; }
        s_Z[j] = Z;
    }
    __syncthreads();

    float acc = 0.f;
    for (int k = 0; k < deg; k++) acc += s_sc[k*HEADS + h] * g_xl[s_src[k]*HD + j];
    acc += s_sc[deg*HEADS + h] * xl_i;
    float val = acc / s_Z[h] + bias_gat[j];

    float mean = blocksum256(val, s_red) * (1.0f / 256.0f);
    float d = val - mean;
    float var = blocksum256(d*d, s_red) * (1.0f / 256.0f);
    g_local[i*HD + j] = d * rsqrtf(var + 1e-5f) * g1[j] + be1[j];
}

// ----------------------------- TF32 tensor-core GEMM (software-pipelined) -----------------------------
// C[M,N] = A[M,K] * op(B) + bias (+GELU).  Double-buffered smem, register prefetch,
// ONE __syncthreads per K-chunk (two-buffer rotation makes the trailing barrier redundant).
template<bool TB, bool ACT>
__global__ void __launch_bounds__(256, 2) k_gemm_tc(const float* __restrict__ A, const float* __restrict__ B,
                                                    const float* __restrict__ bias, float* __restrict__ C,
                                                    int M, int N, int K)
{
    __shared__ unsigned As[2][128][18];
    __shared__ unsigned Bs[2][16][132];
    int bm = blockIdx.y * 128, bn = blockIdx.x * 128;
    int tid = threadIdx.x;
    int wid = tid >> 5, lane = tid & 31;
    int warpm = wid >> 2, warpn = wid & 3;
    int lr = lane >> 2, lc = lane & 3;

    // per-thread load coordinates
    int arow0 = (tid + 0)   >> 2, ac0 = ((tid + 0)   & 3) * 4;
    int arow1 = (tid + 256) >> 2, ac1 = ((tid + 256) & 3) * 4;
    // B (!TB): rows of KxN
    int br0 = (tid + 0)   >> 5, bc0 = ((tid + 0)   & 31) * 4;
    int br1 = (tid + 256) >> 5, bc1 = ((tid + 256) & 31) * 4;
    // B (TB): rows of NxK
    int tn0 = (tid + 0)   >> 2, tk0 = ((tid + 0)   & 3) * 4;
    int tn1 = (tid + 256) >> 2, tk1 = ((tid + 256) & 3) * 4;

    float acc[4][4][4];
    #pragma unroll
    for (int mt = 0; mt < 4; mt++)
        #pragma unroll
        for (int nt = 0; nt < 4; nt++)
            #pragma unroll
            for (int q = 0; q < 4; q++) acc[mt][nt][q] = 0.f;

    float4 apf0, apf1, bpf0, bpf1;

    // prefetch chunk 0
    apf0 = *(const float4*)&A[(size_t)(bm + arow0)*K + ac0];
    apf1 = *(const float4*)&A[(size_t)(bm + arow1)*K + ac1];
    if (!TB) {
        bpf0 = *(const float4*)&B[(size_t)br0*N + bn + bc0];
        bpf1 = *(const float4*)&B[(size_t)br1*N + bn + bc1];
    } else {
        bpf0 = *(const float4*)&B[(size_t)(bn + tn0)*K + tk0];
        bpf1 = *(const float4*)&B[(size_t)(bn + tn1)*K + tk1];
    }

    int nchunks = K >> 4;
    for (int ch = 0; ch < nchunks; ch++) {
        int st = ch & 1;
        // store prefetched chunk into smem (with tf32 conversion)
        As[st][arow0][ac0+0] = tf32cvt(apf0.x); As[st][arow0][ac0+1] = tf32cvt(apf0.y);
        As[st][arow0][ac0+2] = tf32cvt(apf0.z); As[st][arow0][ac0+3] = tf32cvt(apf0.w);
        As[st][arow1][ac1+0] = tf32cvt(apf1.x); As[st][arow1][ac1+1] = tf32cvt(apf1.y);
        As[st][arow1][ac1+2] = tf32cvt(apf1.z); As[st][arow1][ac1+3] = tf32cvt(apf1.w);
        if (!TB) {
            Bs[st][br0][bc0+0] = tf32cvt(bpf0.x); Bs[st][br0][bc0+1] = tf32cvt(bpf0.y);
            Bs[st][br0][bc0+2] = tf32cvt(bpf0.z); Bs[st][br0][bc0+3] = tf32cvt(bpf0.w);
            Bs[st][br1][bc1+0] = tf32cvt(bpf1.x); Bs[st][br1][bc1+1] = tf32cvt(bpf1.y);
            Bs[st][br1][bc1+2] = tf32cvt(bpf1.z); Bs[st][br1][bc1+3] = tf32cvt(bpf1.w);
        } else {
            Bs[st][tk0+0][tn0] = tf32cvt(bpf0.x); Bs[st][tk0+1][tn0] = tf32cvt(bpf0.y);
            Bs[st][tk0+2][tn0] = tf32cvt(bpf0.z); Bs[st][tk0+3][tn0] = tf32cvt(bpf0.w);
            Bs[st][tk1+0][tn1] = tf32cvt(bpf1.x); Bs[st][tk1+1][tn1] = tf32cvt(bpf1.y);
            Bs[st][tk1+2][tn1] = tf32cvt(bpf1.z); Bs[st][tk1+3][tn1] = tf32cvt(bpf1.w);
        }
        __syncthreads();

        // prefetch next chunk (overlaps mma below)
        if (ch + 1 < nchunks) {
            int k0 = (ch + 1) << 4;
            apf0 = *(const float4*)&A[(size_t)(bm + arow0)*K + k0 + ac0];
            apf1 = *(const float4*)&A[(size_t)(bm + arow1)*K + k0 + ac1];
            if (!TB) {
                bpf0 = *(const float4*)&B[(size_t)(k0 + br0)*N + bn + bc0];
                bpf1 = *(const float4*)&B[(size_t)(k0 + br1)*N + bn + bc1];
            } else {
                bpf0 = *(const float4*)&B[(size_t)(bn + tn0)*K + k0 + tk0];
                bpf1 = *(const float4*)&B[(size_t)(bn + tn1)*K + k0 + tk1];
            }
        }

        #pragma unroll
        for (int s = 0; s < 16; s += 8) {
            unsigned af[4][4], bf[4][2];
            #pragma unroll
            for (int mt = 0; mt < 4; mt++) {
                int r0 = warpm*64 + mt*16 + lr;
                af[mt][0] = As[st][r0    ][s + lc];
                af[mt][1] = As[st][r0 + 8][s + lc];
                af[mt][2] = As[st][r0    ][s + 4 + lc];
                af[mt][3] = As[st][r0 + 8][s + 4 + lc];
            }
            #pragma unroll
            for (int nt = 0; nt < 4; nt++) {
                int cn = warpn*32 + nt*8 + lr;
                bf[nt][0] = Bs[st][s + lc    ][cn];
                bf[nt][1] = Bs[st][s + 4 + lc][cn];
            }
            #pragma unroll
            for (int mt = 0; mt < 4; mt++)
                #pragma unroll
                for (int nt = 0; nt < 4; nt++)
                    mma_tf32(acc[mt][nt], af[mt], bf[nt][0], bf[nt][1]);
        }
        // no trailing barrier: next store targets the other buffer, and every warp
        // passed this chunk's barrier only after finishing its read of that buffer.
    }

    #pragma unroll
    for (int mt = 0; mt < 4; mt++) {
        int r0 = bm + warpm*64 + mt*16 + lr;
        #pragma unroll
        for (int nt = 0; nt < 4; nt++) {
            int c0 = bn + warpn*32 + nt*8 + lc*2;
            float b0 = bias[c0], b1 = bias[c0+1];
            float v0 = acc[mt][nt][0] + b0, v1 = acc[mt][nt][1] + b1;
            float v2 = acc[mt][nt][2] + b0, v3 = acc[mt][nt][3] + b1;
            if (ACT) { v0 = geluf(v0); v1 = geluf(v1); v2 = geluf(v2); v3 = geluf(v3); }
            float2 o0 = { v0, v1 }, o1 = { v2, v3 };
            *(float2*)&C[(size_t)r0*N + c0]       = o0;
            *(float2*)&C[(size_t)(r0+8)*N + c0]   = o1;
        }
    }
}

// ----------------------------- TF32 flash attention -----------------------------
#define ATTN_SMEM_BYTES ((18432 + 16512 + 4608 + 16896) * 4)
__global__ void __launch_bounds__(256) k_attn()
{
    extern __shared__ unsigned smu[];
    unsigned* Ks = smu;
    unsigned* Vt = smu + 18432;
    unsigned* Qs = smu + 18432 + 16512;
    unsigned* Ps = smu + 18432 + 16512 + 4608;

    int blk = blockIdx.x;
    int gh = blk >> 1, half = blk & 1;
    int g = gh >> 3, h = gh & 7;
    int tid = threadIdx.x, w = tid >> 5, lane = tid & 31;
    int lr = lane >> 2, lc = lane & 3;
    int gbase = g * NPG;
    const float SCALE = 0.17677669529663687f;  // 1/sqrt(32)

    for (int idx = tid; idx < NPG * CDIM; idx += 256) {
        int row = idx >> 5, c = idx & 31;
        size_t rb = (size_t)(gbase + row) * 768 + h*32 + c;
        Ks[row*36 + c]  = tf32cvt(g_qkv[rb + 256]);
        Vt[c*516 + row] = tf32cvt(g_qkv[rb + 512]);
    }
    __syncthreads();

    for (int qt = 0; qt < 2; qt++) {
        int qrow0 = half*256 + qt*128;
        #pragma unroll
        for (int rr = 0; rr < 16; rr++) {
            int r = w*16 + rr;
            Qs[r*36 + lane] = tf32cvt(g_qkv[(size_t)(gbase + qrow0 + r)*768 + h*32 + lane]);
        }
        __syncwarp();
        unsigned aq[4][4];
        #pragma unroll
        for (int s = 0; s < 4; s++) {
            int rb0 = w*16 + lr;
            aq[s][0] = Qs[rb0*36 + s*8 + lc];
            aq[s][1] = Qs[(rb0+8)*36 + s*8 + lc];
            aq[s][2] = Qs[rb0*36 + s*8 + 4 + lc];
            aq[s][3] = Qs[(rb0+8)*36 + s*8 + 4 + lc];
        }

        float m0 = -1e30f, m1 = -1e30f, l0 = 0.f, l1 = 0.f;
        float oacc[4][4];
        #pragma unroll
        for (int nt = 0; nt < 4; nt++)
            #pragma unroll
            for (int q = 0; q < 4; q++) oacc[nt][q] = 0.f;

        for (int j = 0; j < 4; j++) {
            int jb = j*128;
            float sacc[16][4];
            #pragma unroll
            for (int nt = 0; nt < 16; nt++)
                #pragma unroll
                for (int q = 0; q < 4; q++) sacc[nt][q] = 0.f;

            #pragma unroll
            for (int nt = 0; nt < 16; nt++) {
                int kr = (jb + nt*8 + lr)*36;
                #pragma unroll
                for (int s = 0; s < 4; s++) {
                    unsigned b0 = Ks[kr + s*8 + lc];
                    unsigned b1 = Ks[kr + s*8 + 4 + lc];
                    mma_tf32(sacc[nt], aq[s], b0, b1);
                }
            }

            float cm0 = -1e30f, cm1 = -1e30f;
            #pragma unroll
            for (int nt = 0; nt < 16; nt++) {
                cm0 = fmaxf(cm0, fmaxf(sacc[nt][0], sacc[nt][1]));
                cm1 = fmaxf(cm1, fmaxf(sacc[nt][2], sacc[nt][3]));
            }
            cm0 = fmaxf(cm0, __shfl_xor_sync(0xffffffffu, cm0, 1));
            cm0 = fmaxf(cm0, __shfl_xor_sync(0xffffffffu, cm0, 2));
            cm1 = fmaxf(cm1, __shfl_xor_sync(0xffffffffu, cm1, 1));
            cm1 = fmaxf(cm1, __shfl_xor_sync(0xffffffffu, cm1, 2));

            float nm0 = fmaxf(m0, cm0), nm1 = fmaxf(m1, cm1);
            float sc0 = __expf((m0 - nm0) * SCALE), sc1 = __expf((m1 - nm1) * SCALE);
            m0 = nm0; m1 = nm1;

            float ps0 = 0.f, ps1 = 0.f;
            int pr0 = (w*16 + lr)*132, pr1 = (w*16 + lr + 8)*132;
            #pragma unroll
            for (int nt = 0; nt < 16; nt++) {
                float p0 = __expf((sacc[nt][0] - nm0) * SCALE);
                float p1 = __expf((sacc[nt][1] - nm0) * SCALE);
                float p2 = __expf((sacc[nt][2] - nm1) * SCALE);
                float p3 = __expf((sacc[nt][3] - nm1) * SCALE);
                ps0 += p0 + p1; ps1 += p2 + p3;
                int cc = nt*8 + 2*lc;
                Ps[pr0 + cc]     = tf32cvt(p0);
                Ps[pr0 + cc + 1] = tf32cvt(p1);
                Ps[pr1 + cc]     = tf32cvt(p2);
                Ps[pr1 + cc + 1] = tf32cvt(p3);
            }
            ps0 += __shfl_xor_sync(0xffffffffu, ps0, 1);
            ps0 += __shfl_xor_sync(0xffffffffu, ps0, 2);
            ps1 += __shfl_xor_sync(0xffffffffu, ps1, 1);
            ps1 += __shfl_xor_sync(0xffffffffu, ps1, 2);
            l0 = l0 * sc0 + ps0;
            l1 = l1 * sc1 + ps1;
            #pragma unroll
            for (int nt = 0; nt < 4; nt++) {
                oacc[nt][0] *= sc0; oacc[nt][1] *= sc0;
                oacc[nt][2] *= sc1; oacc[nt][3] *= sc1;
            }
            __syncwarp();

            #pragma unroll
            for (int s2 = 0; s2 < 16; s2++) {
                unsigned ap[4];
                int pb0 = (w*16 + lr)*132 + s2*8;
                int pb1 = (w*16 + lr + 8)*132 + s2*8;
                ap[0] = Ps[pb0 + lc];     ap[1] = Ps[pb1 + lc];
                ap[2] = Ps[pb0 + 4 + lc]; ap[3] = Ps[pb1 + 4 + lc];
                #pragma unroll
                for (int nt2 = 0; nt2 < 4; nt2++) {
                    int vb = (nt2*8 + lr)*516 + jb + s2*8;
                    mma_tf32(oacc[nt2], ap, Vt[vb + lc], Vt[vb + 4 + lc]);
                }
            }
            __syncwarp();
        }

        float inv0 = 1.0f / l0, inv1 = 1.0f / l1;
        int row0 = gbase + qrow0 + w*16 + lr;
        #pragma unroll
        for (int nt2 = 0; nt2 < 4; nt2++) {
            int col = h*32 + nt2*8 + 2*lc;
            float2 o0 = { oacc[nt2][0]*inv0, oacc[nt2][1]*inv0 };
            float2 o1 = { oacc[nt2][2]*inv1, oacc[nt2][3]*inv1 };
            *(float2*)&g_attno[(size_t)row0*HD + col]       = o0;
            *(float2*)&g_attno[(size_t)(row0+8)*HD + col]   = o1;
        }
        __syncwarp();
    }
}

// ----------------------------- LN2 + combine -----------------------------
__global__ void __launch_bounds__(256) k_combine(const float* __restrict__ g2, const float* __restrict__ be2,
                                                 const float* __restrict__ alpha_p)
{
    __shared__ float red[8];
    int i = blockIdx.x, j = threadIdx.x;
    float g = g_graw[i*HD + j];
    float mean = blocksum256(g, red) * (1.0f / 256.0f);
    float d = g - mean;
    float var = blocksum256(d*d, red) * (1.0f / 256.0f);
    float y = d * rsqrtf(var + 1e-5f) * g2[j] + be2[j];
    float a = 1.0f / (1.0f + __expf(-alpha_p[0]));
    g_comb[i*HD + j] = a * g_local[i*HD + j] + (1.0f - a) * y;
}

// ----------------------------- residual + LN3 -> out -----------------------------
__global__ void __launch_bounds__(256) k_final(const float* __restrict__ g3, const float* __restrict__ be3,
                                               float* __restrict__ out)
{
    __shared__ float red[8];
    int i = blockIdx.x, j = threadIdx.x;
    float v = g_comb[i*HD + j] + g_f2[i*HD + j];
    float mean = blocksum256(v, red) * (1.0f / 256.0f);
    float d = v - mean;
    float var = blocksum256(d*d, red) * (1.0f / 256.0f);
    out[i*HD + j] = d * rsqrtf(var + 1e-5f) * g3[j] + be3[j];
}

// ----------------------------- launch -----------------------------
extern "C" void kernel_launch(void* const* d_in, const int* in_sizes, int n_in,
                              void* d_out, int out_size)
{
    const float* x        = (const float*)d_in[0];
    const float* ea       = (const float*)d_in[1];
    const float* W_l      = (const float*)d_in[2];
    const float* b_l      = (const float*)d_in[3];
    const float* W_r      = (const float*)d_in[4];
    const float* b_r      = (const float*)d_in[5];
    const float* W_e      = (const float*)d_in[6];
    const float* att      = (const float*)d_in[7];
    const float* bias_gat = (const float*)d_in[8];
    const float* ipw      = (const float*)d_in[9];
    const float* ipb      = (const float*)d_in[10];
    const float* opw      = (const float*)d_in[11];
    const float* opb      = (const float*)d_in[12];
    const float* alpha    = (const float*)d_in[13];
    const float* W1       = (const float*)d_in[14];
    const float* b1       = (const float*)d_in[15];
    const float* W2       = (const float*)d_in[16];
    const float* b2       = (const float*)d_in[17];
    const float* g1       = (const float*)d_in[18];
    const float* be1      = (const float*)d_in[19];
    const float* g2       = (const float*)d_in[20];
    const float* be2      = (const float*)d_in[21];
    const float* g3       = (const float*)d_in[22];
    const float* be3      = (const float*)d_in[23];
    const int*   ei       = (const int*)d_in[24];
    float* out = (float*)d_out;

    float *xl, *xr, *qkv, *attno, *graw, *comb, *h1, *f2;
    cudaGetSymbolAddress((void**)&xl,    g_xl);
    cudaGetSymbolAddress((void**)&xr,    g_xr);
    cudaGetSymbolAddress((void**)&qkv,   g_qkv);
    cudaGetSymbolAddress((void**)&attno, g_attno);
    cudaGetSymbolAddress((void**)&graw,  g_graw);
    cudaGetSymbolAddress((void**)&comb,  g_comb);
    cudaGetSymbolAddress((void**)&h1,    g_h1);
    cudaGetSymbolAddress((void**)&f2,    g_f2);

    cudaFuncSetAttribute(k_attn, cudaFuncAttributeMaxDynamicSharedMemorySize, ATTN_SMEM_BYTES);

    // graph prep + GAT path
    k_zero<<<(NTOT + 255)/256, 256>>>();
    k_gemm_tc<false,false><<<dim3(HD/128, NTOT/128), 256>>>(x, W_l, b_l, xl, NTOT, HD, HD);
    k_gemm_tc<false,false><<<dim3(HD/128, NTOT/128), 256>>>(x, W_r, b_r, xr, NTOT, HD, HD);
    k_edgecnt<<<(EDG + 255)/256, 256>>>(ei, ea);
    k_scan<<<1, 1024>>>();
    k_fill<<<(EDG + 255)/256, 256>>>(ei);
    k_gat<<<NTOT, 256>>>(ei, ea, W_e, att, bias_gat, g1, be1);

    // global attention path
    k_gemm_tc<true,false><<<dim3(3*HD/128, NTOT/128), 256>>>(x, ipw, ipb, qkv, NTOT, 3*HD, HD);
    k_attn<<<GRAPHS*HEADS*2, 256, ATTN_SMEM_BYTES>>>();
    k_gemm_tc<true,false><<<dim3(HD/128, NTOT/128), 256>>>(attno, opw, opb, graw, NTOT, HD, HD);

    // combine + FFN + final LN
    k_combine<<<NTOT, 256>>>(g2, be2, alpha);
    k_gemm_tc<false,true ><<<dim3(4*HD/128, NTOT/128), 256>>>(comb, W1, b1, h1, NTOT, 4*HD, HD);
    k_gemm_tc<false,false><<<dim3(HD/128, NTOT/128), 256>>>(h1, W2, b2, f2, NTOT, HD, 4*HD);
    k_final<<<NTOT, 256>>>(g3, be3, out);

    (void)in_sizes; (void)n_in; (void)out_size;
}